// round 8
// baseline (speedup 1.0000x reference)
#include <cuda_runtime.h>
#include <cuda_bf16.h>
#include <cstdint>
#include <cstddef>

// CompetitiveNetwork via mma.sync (m16n8k16 bf16, fp32 accum).
// R7: warp-pair col-split. Each m16 row-tile is owned by TWO warps: warp
// (2p) computes output cols [0,32), warp (2p+1) cols [32,64). Halves the
// per-warp MMA/MUFU chain and doubles warps/SMSP to 4 (512 thr/CTA). After
// each matvec, each warp splits its D half into the A-fragment kts its cols
// map to (cols c -> k=c: exactly 2 of 4 kts) and exchanges packed bf16
// fragments with its partner through a parity double-buffered smem ring +
// one named barrier per matvec (no extra rounding: exchange is post-pack).
// Precision schedule unchanged from R6: 14 cheap + 4 precise iterations.

#define THREADS 512
#define ROWS_PER_CTA 128
#define N_DIM 64
#define CHEAP_ITERS 14
#define PREC_ITERS 4

typedef unsigned int u32;

// smem map
#define MATS_BYTES (6 * 8192)                   // 49152: fragment-ordered mats
#define ATS_OFF    MATS_BYTES
#define AT_STRIDE  66
#define ATS_BYTES  (128 * AT_STRIDE * 4)        // 33792
#define XBUF_OFF   (ATS_OFF + ATS_BYTES)        // 82944
#define XBUF_BYTES (32 * 512 * 4)               // 65536: 32 planes x 512 words
#define PS_OFF     (XBUF_OFF + XBUF_BYTES)      // 148480
#define SMEM_TOTAL (PS_OFF + 256 * 4)           // 149504

__device__ __forceinline__ float rcpa(float x) {
    float r; asm("rcp.approx.f32 %0, %1;" : "=f"(r) : "f"(x)); return r;
}
__device__ __forceinline__ u32 packbf(float lo_elem, float hi_elem) {
    u32 r; asm("cvt.rn.bf16x2.f32 %0, %1, %2;" : "=r"(r)
               : "f"(hi_elem), "f"(lo_elem));
    return r;
}
__device__ __forceinline__ void split2(float x0, float x1, u32 &hi, u32 &lo) {
    hi = packbf(x0, x1);
    float h0 = __uint_as_float(hi << 16);
    float h1 = __uint_as_float(hi & 0xFFFF0000u);
    lo = packbf(x0 - h0, x1 - h1);
}

// fragment-order store: element at logical (k, n) of a B operand
__device__ __forceinline__ void st_frag(__nv_bfloat16* base, int k, int n,
                                        __nv_bfloat16 v) {
    int lane = ((n & 7) << 2) | ((k & 7) >> 1);
    int w2   = (((k >> 4) & 1) << 1) | ((k >> 3) & 1);
    int idx  = ((k >> 5) << 11) | ((n >> 3) << 8) | (lane << 3)
             | (w2 << 1) | (k & 1);
    base[idx] = v;
}

#define MMA(d, a, b0, b1)                                                      \
    asm("mma.sync.aligned.m16n8k16.row.col.f32.bf16.bf16.f32 "                 \
        "{%0,%1,%2,%3}, {%4,%5,%6,%7}, {%8,%9}, {%0,%1,%2,%3};"                \
        : "+f"((d)[0]), "+f"((d)[1]), "+f"((d)[2]), "+f"((d)[3])               \
        : "r"((a)[0]), "r"((a)[1]), "r"((a)[2]), "r"((a)[3]),                  \
          "r"(b0), "r"(b1))

#define PAIR_BAR() asm volatile("bar.sync %0, %1;"                             \
                                :: "r"(pair + 1), "r"(64) : "memory")

__global__ void __launch_bounds__(THREADS, 1)
cnet_mma_kernel(const float* __restrict__ AT,
                const float* __restrict__ Kraw,
                const float* __restrict__ BTraw,
                const float* __restrict__ Wraw,
                const float* __restrict__ braw,
                float* __restrict__ out)
{
    extern __shared__ char smc[];
    __nv_bfloat16* mats = reinterpret_cast<__nv_bfloat16*>(smc);
    float* ats = reinterpret_cast<float*>(smc + ATS_OFF);   // [128][66] f32
    u32*   xbuf = reinterpret_cast<u32*>(smc + XBUF_OFF);   // [32][16][32]
    float* PS   = reinterpret_cast<float*>(smc + PS_OFF);   // [16][16]

    const int tid  = threadIdx.x;
    const int wid  = tid >> 5;          // 0..15
    const int lane = tid & 31;
    const int g    = lane >> 2;         // 0..7
    const int t    = lane & 3;          // 0..3
    const int pair = wid >> 1;          // row-tile 0..7 -> rows [16p,16p+16)
    const int half = wid & 1;           // 0: cols [0,32), 1: cols [32,64)
    const int c0   = half * 32;
    const int ntb  = half * 4;          // global nt base for this warp
    const int kb   = half * 2;          // own A-frag kts: kb, kb+1
    const int pkb  = 2 - kb;            // partner's kts
    const int pwid = wid ^ 1;
    const int rb   = pair * 16;
    const int bid  = blockIdx.x;

    // ---- setup: exp/clip K, fragment-ordered split B matrices + AT tile ----
    for (int idx = tid; idx < 4096; idx += THREADS) {
        int i = idx >> 6, j = idx & 63;
        float k = fminf(__expf(Kraw[idx]), 1000.0f);
        float wv = fminf(fmaxf(Wraw[idx], -10.0f), 10.0f);
        float m = k * wv;
        __nv_bfloat16 kh = __float2bfloat16_rn(k);
        __nv_bfloat16 kl = __float2bfloat16_rn(k - __bfloat162float(kh));
        __nv_bfloat16 mh = __float2bfloat16_rn(m);
        __nv_bfloat16 ml = __float2bfloat16_rn(m - __bfloat162float(mh));
        st_frag(mats + 0 * 4096, i, j, kh);   // KT hi (BF-step)
        st_frag(mats + 1 * 4096, i, j, kl);   // KT lo
        st_frag(mats + 2 * 4096, j, i, kh);   // K  hi (AF-step)
        st_frag(mats + 3 * 4096, j, i, kl);   // K  lo
        st_frag(mats + 4 * 4096, i, j, mh);   // MT hi (epilogue)
        st_frag(mats + 5 * 4096, i, j, ml);   // MT lo
    }
    {
        const float4* atg = reinterpret_cast<const float4*>(
            AT + (size_t)bid * (ROWS_PER_CTA * N_DIM));
        for (int idx = tid; idx < 2048; idx += THREADS) {
            float4 v = atg[idx];
            int r = idx >> 4, c = (idx & 15) << 2;
            float* p = ats + r * AT_STRIDE + c;
            p[0] = v.x; p[1] = v.y; p[2] = v.z; p[3] = v.w;
        }
    }
    // BT cache for own cols: col = c0 + 8*ntl + 2t + h
    float btv[8];
    #pragma unroll
    for (int ntl = 0; ntl < 4; ntl++) {
        btv[2 * ntl + 0] = fminf(__expf(BTraw[c0 + 8 * ntl + 2 * t + 0]), 1000.0f);
        btv[2 * ntl + 1] = fminf(__expf(BTraw[c0 + 8 * ntl + 2 * t + 1]), 1000.0f);
    }
    __syncthreads();

    // ---- fragment registers -------------------------------------------------
    float d[4][4];            // D frags for own 4 nt
    u32 ah[4][4], al[4][4];   // full-k A frags (kts kb,kb+1 computed; others exchanged)

    const int rlo = (rb + g) * AT_STRIDE;
    const int rhi = (rb + 8 + g) * AT_STRIDE;

    // initial A = split(AT): both warps of a pair build identical full frags
    #pragma unroll
    for (int kt = 0; kt < 4; kt++) {
        int cb = 16 * kt + 2 * t;
        float2 p0 = *reinterpret_cast<const float2*>(ats + rlo + cb);
        float2 p1 = *reinterpret_cast<const float2*>(ats + rhi + cb);
        float2 p2 = *reinterpret_cast<const float2*>(ats + rlo + cb + 8);
        float2 p3 = *reinterpret_cast<const float2*>(ats + rhi + cb + 8);
        split2(p0.x, p0.y, ah[kt][0], al[kt][0]);
        split2(p1.x, p1.y, ah[kt][1], al[kt][1]);
        split2(p2.x, p2.y, ah[kt][2], al[kt][2]);
        split2(p3.x, p3.y, ah[kt][3], al[kt][3]);
    }

    // per-thread fragment pointer: uint4 idx = mat*512 + sel*256 + nt*32 + lane
    const uint4* __restrict__ frag = reinterpret_cast<const uint4*>(smc) + lane;

    int xp = 0;   // exchange parity plane base (0 or 16)

#define MMA_PHASE_CHEAP(MH)                                                    \
    do {                                                                       \
        _Pragma("unroll")                                                      \
        for (int ntl = 0; ntl < 4; ntl++)                                      \
            _Pragma("unroll")                                                  \
            for (int c = 0; c < 4; c++) d[ntl][c] = 0.0f;                      \
        _Pragma("unroll")                                                      \
        for (int sel = 0; sel < 2; sel++) {                                    \
            _Pragma("unroll")                                                  \
            for (int ntl = 0; ntl < 4; ntl++) {                                \
                uint4 h = frag[(MH) * 512 + sel * 256 + (ntb + ntl) * 32];     \
                MMA(d[ntl], ah[2*sel],   h.x, h.y);                            \
                MMA(d[ntl], ah[2*sel+1], h.z, h.w);                            \
            }                                                                  \
        }                                                                      \
    } while (0)

#define MMA_PHASE_FULL(MH)                                                     \
    do {                                                                       \
        _Pragma("unroll")                                                      \
        for (int ntl = 0; ntl < 4; ntl++)                                      \
            _Pragma("unroll")                                                  \
            for (int c = 0; c < 4; c++) d[ntl][c] = 0.0f;                      \
        _Pragma("unroll")                                                      \
        for (int sel = 0; sel < 2; sel++) {                                    \
            _Pragma("unroll")                                                  \
            for (int ntl = 0; ntl < 4; ntl++) {                                \
                uint4 h = frag[(MH) * 512 + sel * 256 + (ntb + ntl) * 32];     \
                uint4 l = frag[((MH)+1) * 512 + sel * 256 + (ntb + ntl) * 32]; \
                MMA(d[ntl], ah[2*sel],   h.x, h.y);                            \
                MMA(d[ntl], al[2*sel],   h.x, h.y);                            \
                MMA(d[ntl], ah[2*sel],   l.x, l.y);                            \
                MMA(d[ntl], ah[2*sel+1], h.z, h.w);                            \
                MMA(d[ntl], al[2*sel+1], h.z, h.w);                            \
                MMA(d[ntl], ah[2*sel+1], l.z, l.w);                            \
            }                                                                  \
        }                                                                      \
    } while (0)

#define BF_NONLIN()                                                            \
    do {                                                                       \
        _Pragma("unroll")                                                      \
        for (int ntl = 0; ntl < 4; ntl++) {                                    \
            d[ntl][0] = btv[2*ntl+0] * rcpa(d[ntl][0] + 1.0f);                 \
            d[ntl][1] = btv[2*ntl+1] * rcpa(d[ntl][1] + 1.0f);                 \
            d[ntl][2] = btv[2*ntl+0] * rcpa(d[ntl][2] + 1.0f);                 \
            d[ntl][3] = btv[2*ntl+1] * rcpa(d[ntl][3] + 1.0f);                 \
        }                                                                      \
    } while (0)

#define AF_NONLIN()                                                            \
    do {                                                                       \
        _Pragma("unroll")                                                      \
        for (int ntl = 0; ntl < 4; ntl++) {                                    \
            int cb = c0 + 8 * ntl + 2 * t;                                     \
            float2 plo = *reinterpret_cast<const float2*>(ats + rlo + cb);     \
            float2 phi = *reinterpret_cast<const float2*>(ats + rhi + cb);     \
            d[ntl][0] = plo.x * rcpa(d[ntl][0] + 1.0f);                        \
            d[ntl][1] = plo.y * rcpa(d[ntl][1] + 1.0f);                        \
            d[ntl][2] = phi.x * rcpa(d[ntl][2] + 1.0f);                        \
            d[ntl][3] = phi.y * rcpa(d[ntl][3] + 1.0f);                        \
        }                                                                      \
    } while (0)

    // own-cols repack (cheap: hi only), then exchange with partner
#define REPACK_XCHG_CHEAP()                                                    \
    do {                                                                       \
        ah[kb+0][0] = packbf(d[0][0], d[0][1]);                                \
        ah[kb+0][1] = packbf(d[0][2], d[0][3]);                                \
        ah[kb+0][2] = packbf(d[1][0], d[1][1]);                                \
        ah[kb+0][3] = packbf(d[1][2], d[1][3]);                                \
        ah[kb+1][0] = packbf(d[2][0], d[2][1]);                                \
        ah[kb+1][1] = packbf(d[2][2], d[2][3]);                                \
        ah[kb+1][2] = packbf(d[3][0], d[3][1]);                                \
        ah[kb+1][3] = packbf(d[3][2], d[3][3]);                                \
        _Pragma("unroll")                                                      \
        for (int i = 0; i < 8; i++)                                            \
            xbuf[(xp + i) * 512 + wid * 32 + lane] = ah[kb + (i >> 2)][i & 3]; \
        PAIR_BAR();                                                            \
        _Pragma("unroll")                                                      \
        for (int i = 0; i < 8; i++)                                            \
            ah[pkb + (i >> 2)][i & 3] = xbuf[(xp + i) * 512 + pwid * 32 + lane];\
        xp ^= 16;                                                              \
    } while (0)

    // full repack (hi + lo) + exchange
#define REPACK_XCHG_FULL()                                                     \
    do {                                                                       \
        split2(d[0][0], d[0][1], ah[kb+0][0], al[kb+0][0]);                    \
        split2(d[0][2], d[0][3], ah[kb+0][1], al[kb+0][1]);                    \
        split2(d[1][0], d[1][1], ah[kb+0][2], al[kb+0][2]);                    \
        split2(d[1][2], d[1][3], ah[kb+0][3], al[kb+0][3]);                    \
        split2(d[2][0], d[2][1], ah[kb+1][0], al[kb+1][0]);                    \
        split2(d[2][2], d[2][3], ah[kb+1][1], al[kb+1][1]);                    \
        split2(d[3][0], d[3][1], ah[kb+1][2], al[kb+1][2]);                    \
        split2(d[3][2], d[3][3], ah[kb+1][3], al[kb+1][3]);                    \
        _Pragma("unroll")                                                      \
        for (int i = 0; i < 8; i++) {                                          \
            xbuf[(xp + i) * 512 + wid * 32 + lane] = ah[kb + (i >> 2)][i & 3]; \
            xbuf[(xp + 8 + i) * 512 + wid * 32 + lane] =                       \
                al[kb + (i >> 2)][i & 3];                                      \
        }                                                                      \
        PAIR_BAR();                                                            \
        _Pragma("unroll")                                                      \
        for (int i = 0; i < 8; i++) {                                          \
            ah[pkb + (i >> 2)][i & 3] = xbuf[(xp + i) * 512 + pwid * 32 + lane];\
            al[pkb + (i >> 2)][i & 3] =                                        \
                xbuf[(xp + 8 + i) * 512 + pwid * 32 + lane];                   \
        }                                                                      \
        xp ^= 16;                                                              \
    } while (0)

    // ---- phase 1: convergence iterations, single-MMA bf16 ------------------
    #pragma unroll 1
    for (int it = 0; it < CHEAP_ITERS; ++it) {
        MMA_PHASE_CHEAP(0);   // BF-step (B = KT hi)
        BF_NONLIN();
        REPACK_XCHG_CHEAP();  // A <- BF (hi only)
        MMA_PHASE_CHEAP(2);   // AF-step (B = K hi)
        AF_NONLIN();
        REPACK_XCHG_CHEAP();  // A <- AF (hi only)
    }

    // precision boundary: al stale from initial AT split -> zero
    #pragma unroll
    for (int kt = 0; kt < 4; kt++)
        #pragma unroll
        for (int r = 0; r < 4; r++) al[kt][r] = 0u;

    // ---- phase 2: precision iterations, 3-term split ------------------------
    #pragma unroll 1
    for (int it = 0; it < PREC_ITERS; ++it) {
        MMA_PHASE_FULL(0);    // BF-step
        BF_NONLIN();
        if (it == PREC_ITERS - 1) break;  // d = final BF; ah/al = final AF
        REPACK_XCHG_FULL();   // A <- BF
        MMA_PHASE_FULL(2);    // AF-step
        AF_NONLIN();
        REPACK_XCHG_FULL();   // A <- AF
    }

    // ---- stash final BF (own cols, fp32) into the AT region (AT is dead) ---
    #pragma unroll
    for (int ntl = 0; ntl < 4; ntl++) {
        int cb = c0 + 8 * ntl + 2 * t;
        *reinterpret_cast<float2*>(ats + rlo + cb) =
            make_float2(d[ntl][0], d[ntl][1]);
        *reinterpret_cast<float2*>(ats + rhi + cb) =
            make_float2(d[ntl][2], d[ntl][3]);
    }

    // ---- epilogue: H = AF @ M (own cols); y partial = sum_own BF*H ----------
    MMA_PHASE_FULL(4);

    float y0 = 0.f, y1 = 0.f;
    #pragma unroll
    for (int ntl = 0; ntl < 4; ntl++) {
        int cb = c0 + 8 * ntl + 2 * t;
        float2 blo = *reinterpret_cast<const float2*>(ats + rlo + cb);
        float2 bhi = *reinterpret_cast<const float2*>(ats + rhi + cb);
        y0 = fmaf(blo.x, d[ntl][0], fmaf(blo.y, d[ntl][1], y0));
        y1 = fmaf(bhi.x, d[ntl][2], fmaf(bhi.y, d[ntl][3], y1));
    }
    y0 += __shfl_xor_sync(0xFFFFFFFFu, y0, 1);
    y0 += __shfl_xor_sync(0xFFFFFFFFu, y0, 2);
    y1 += __shfl_xor_sync(0xFFFFFFFFu, y1, 1);
    y1 += __shfl_xor_sync(0xFFFFFFFFu, y1, 2);

    if (t == 0) {
        PS[wid * 16 + g]     = y0;
        PS[wid * 16 + g + 8] = y1;
    }
    __syncthreads();

    if (tid < ROWS_PER_CTA) {
        int p = tid >> 4, rl = tid & 15;
        float bc = fminf(fmaxf(braw[0], -10.0f), 10.0f);
        out[(size_t)bid * ROWS_PER_CTA + tid] =
            PS[(2 * p) * 16 + rl] + PS[(2 * p + 1) * 16 + rl] + bc;
    }
}

extern "C" void kernel_launch(void* const* d_in, const int* in_sizes, int n_in,
                              void* d_out, int out_size)
{
    const float* AT    = (const float*)d_in[0];
    const float* Kraw  = (const float*)d_in[1];
    const float* BTraw = (const float*)d_in[2];
    const float* Wraw  = (const float*)d_in[3];
    const float* braw  = (const float*)d_in[4];
    float* out = (float*)d_out;

    const int B = in_sizes[0] / N_DIM;          // 16384
    const int grid = B / ROWS_PER_CTA;          // 128

    cudaFuncSetAttribute(cnet_mma_kernel,
                         cudaFuncAttributeMaxDynamicSharedMemorySize,
                         SMEM_TOTAL);

    cnet_mma_kernel<<<grid, THREADS, SMEM_TOTAL>>>(
        AT, Kraw, BTraw, Wraw, braw, out);
}

// round 9
// speedup vs baseline: 1.1799x; 1.1799x over previous
#include <cuda_runtime.h>
#include <cuda_bf16.h>
#include <cstdint>
#include <cstddef>

// CompetitiveNetwork via mma.sync (m16n8k16 bf16, fp32 accum).
// R8: revert R7's cross-warp exchange (smem round-trip regressed; L1 70%).
// Back to R6 topology (8 warps/CTA, 16 rows/warp, state in registers, no
// syncs in loop) with a fused per-group pipeline: each matvec is 4
// independent chains of (8 MMAs -> 8 rcps -> 4 packs) over ping-pong A-frag
// buffers, plus zero-accumulator first MMAs (no d zero-init). Shorter chains
// + ILP + lower register pressure. 14 cheap + 4 precise iterations.

#define THREADS 256
#define ROWS_PER_CTA 128
#define N_DIM 64
#define CHEAP_ITERS 14

typedef unsigned int u32;

#define MATS_BYTES (6 * 8192)              // fragment-ordered split matrices
#define AT_OFF     MATS_BYTES
#define AT_STRIDE  66
#define SMEM_TOTAL (AT_OFF + 128 * AT_STRIDE * 4)   // 82944

__device__ __forceinline__ float rcpa(float x) {
    float r; asm("rcp.approx.f32 %0, %1;" : "=f"(r) : "f"(x)); return r;
}
__device__ __forceinline__ u32 packbf(float lo_elem, float hi_elem) {
    u32 r; asm("cvt.rn.bf16x2.f32 %0, %1, %2;" : "=r"(r)
               : "f"(hi_elem), "f"(lo_elem));
    return r;
}
__device__ __forceinline__ void split2(float x0, float x1, u32 &hi, u32 &lo) {
    hi = packbf(x0, x1);
    float h0 = __uint_as_float(hi << 16);
    float h1 = __uint_as_float(hi & 0xFFFF0000u);
    lo = packbf(x0 - h0, x1 - h1);
}

// fragment-order store: element at logical (k, n) of a B operand
__device__ __forceinline__ void st_frag(__nv_bfloat16* base, int k, int n,
                                        __nv_bfloat16 v) {
    int lane = ((n & 7) << 2) | ((k & 7) >> 1);
    int w2   = (((k >> 4) & 1) << 1) | ((k >> 3) & 1);
    int idx  = ((k >> 5) << 11) | ((n >> 3) << 8) | (lane << 3)
             | (w2 << 1) | (k & 1);
    base[idx] = v;
}

#define MMA(d, a, b0, b1)                                                      \
    asm("mma.sync.aligned.m16n8k16.row.col.f32.bf16.bf16.f32 "                 \
        "{%0,%1,%2,%3}, {%4,%5,%6,%7}, {%8,%9}, {%0,%1,%2,%3};"                \
        : "+f"((d)[0]), "+f"((d)[1]), "+f"((d)[2]), "+f"((d)[3])               \
        : "r"((a)[0]), "r"((a)[1]), "r"((a)[2]), "r"((a)[3]),                  \
          "r"(b0), "r"(b1))

// first MMA of an accumulator: D = A*B + 0 (no zero-init movs)
#define MMA_Z(d, a, b0, b1)                                                    \
    asm("mma.sync.aligned.m16n8k16.row.col.f32.bf16.bf16.f32 "                 \
        "{%0,%1,%2,%3}, {%4,%5,%6,%7}, {%8,%9}, {%10,%10,%10,%10};"            \
        : "=f"((d)[0]), "=f"((d)[1]), "=f"((d)[2]), "=f"((d)[3])               \
        : "r"((a)[0]), "r"((a)[1]), "r"((a)[2]), "r"((a)[3]),                  \
          "r"(b0), "r"(b1), "f"(0.0f))

__global__ void __launch_bounds__(THREADS, 1)
cnet_mma_kernel(const float* __restrict__ AT,
                const float* __restrict__ Kraw,
                const float* __restrict__ BTraw,
                const float* __restrict__ Wraw,
                const float* __restrict__ braw,
                float* __restrict__ out)
{
    extern __shared__ char smc[];
    __nv_bfloat16* mats = reinterpret_cast<__nv_bfloat16*>(smc);
    float* ats = reinterpret_cast<float*>(smc + AT_OFF);   // [128][66] f32

    const int tid  = threadIdx.x;
    const int w    = tid >> 5;          // warp 0..7 -> rows [16w, 16w+16)
    const int lane = tid & 31;
    const int g    = lane >> 2;
    const int t    = lane & 3;
    const int rb   = w * 16;
    const int bid  = blockIdx.x;

    // ---- setup: exp/clip K, fragment-ordered split B matrices + AT tile ----
    for (int idx = tid; idx < 4096; idx += THREADS) {
        int i = idx >> 6, j = idx & 63;
        float k = fminf(__expf(Kraw[idx]), 1000.0f);
        float wv = fminf(fmaxf(Wraw[idx], -10.0f), 10.0f);
        float m = k * wv;
        __nv_bfloat16 kh = __float2bfloat16_rn(k);
        __nv_bfloat16 kl = __float2bfloat16_rn(k - __bfloat162float(kh));
        __nv_bfloat16 mh = __float2bfloat16_rn(m);
        __nv_bfloat16 ml = __float2bfloat16_rn(m - __bfloat162float(mh));
        st_frag(mats + 0 * 4096, i, j, kh);   // KT hi (BF-step)
        st_frag(mats + 1 * 4096, i, j, kl);   // KT lo
        st_frag(mats + 2 * 4096, j, i, kh);   // K  hi (AF-step)
        st_frag(mats + 3 * 4096, j, i, kl);   // K  lo
        st_frag(mats + 4 * 4096, i, j, mh);   // MT hi (epilogue)
        st_frag(mats + 5 * 4096, i, j, ml);   // MT lo
    }
    {
        const float4* atg = reinterpret_cast<const float4*>(
            AT + (size_t)bid * (ROWS_PER_CTA * N_DIM));
        for (int idx = tid; idx < 2048; idx += THREADS) {
            float4 v = atg[idx];
            int r = idx >> 4, c = (idx & 15) << 2;
            float* p = ats + r * AT_STRIDE + c;
            p[0] = v.x; p[1] = v.y; p[2] = v.z; p[3] = v.w;
        }
    }
    float btv[16];
    #pragma unroll
    for (int nt = 0; nt < 8; nt++) {
        btv[2 * nt + 0] = fminf(__expf(BTraw[8 * nt + 2 * t + 0]), 1000.0f);
        btv[2 * nt + 1] = fminf(__expf(BTraw[8 * nt + 2 * t + 1]), 1000.0f);
    }
    __syncthreads();

    const int rlo = (rb + g) * AT_STRIDE;
    const int rhi = (rb + 8 + g) * AT_STRIDE;

    // ---- A fragments: ping-pong hi buffers + lo buffers (precise phase) ----
    u32 ahA[4][4], ahB[4][4], alA[4][4], alB[4][4];

    // initial A = bf16(AT) (hi only; lo starts at the precision boundary)
    #pragma unroll
    for (int kt = 0; kt < 4; kt++) {
        int cb = 16 * kt + 2 * t;
        float2 p0 = *reinterpret_cast<const float2*>(ats + rlo + cb);
        float2 p1 = *reinterpret_cast<const float2*>(ats + rhi + cb);
        float2 p2 = *reinterpret_cast<const float2*>(ats + rlo + cb + 8);
        float2 p3 = *reinterpret_cast<const float2*>(ats + rhi + cb + 8);
        ahA[kt][0] = packbf(p0.x, p0.y);
        ahA[kt][1] = packbf(p1.x, p1.y);
        ahA[kt][2] = packbf(p2.x, p2.y);
        ahA[kt][3] = packbf(p3.x, p3.y);
    }

    const uint4* __restrict__ frag = reinterpret_cast<const uint4*>(smc) + lane;

    // ---- fused per-group step macros ----------------------------------------
    // group gg handles nt pair (2gg, 2gg+1), produces new A-frag kt=gg.
    // ISBF=1: BF nonlin (btv scale); ISBF=0: AF nonlin (AT from smem).

#define GROUP_NONLIN(ISBF, gg, d0, d1, e0,e1,e2,e3, f0,f1,f2,f3)               \
    do {                                                                       \
        if (ISBF) {                                                            \
            e0 = btv[4*(gg)+0] * rcpa(d0[0] + 1.0f);                           \
            e1 = btv[4*(gg)+1] * rcpa(d0[1] + 1.0f);                           \
            e2 = btv[4*(gg)+0] * rcpa(d0[2] + 1.0f);                           \
            e3 = btv[4*(gg)+1] * rcpa(d0[3] + 1.0f);                           \
            f0 = btv[4*(gg)+2] * rcpa(d1[0] + 1.0f);                           \
            f1 = btv[4*(gg)+3] * rcpa(d1[1] + 1.0f);                           \
            f2 = btv[4*(gg)+2] * rcpa(d1[2] + 1.0f);                           \
            f3 = btv[4*(gg)+3] * rcpa(d1[3] + 1.0f);                           \
        } else {                                                               \
            int cb = 16 * (gg) + 2 * t;                                        \
            float2 plo0 = *reinterpret_cast<const float2*>(ats + rlo + cb);    \
            float2 phi0 = *reinterpret_cast<const float2*>(ats + rhi + cb);    \
            float2 plo1 = *reinterpret_cast<const float2*>(ats + rlo + cb + 8);\
            float2 phi1 = *reinterpret_cast<const float2*>(ats + rhi + cb + 8);\
            e0 = plo0.x * rcpa(d0[0] + 1.0f);                                  \
            e1 = plo0.y * rcpa(d0[1] + 1.0f);                                  \
            e2 = phi0.x * rcpa(d0[2] + 1.0f);                                  \
            e3 = phi0.y * rcpa(d0[3] + 1.0f);                                  \
            f0 = plo1.x * rcpa(d1[0] + 1.0f);                                  \
            f1 = plo1.y * rcpa(d1[1] + 1.0f);                                  \
            f2 = phi1.x * rcpa(d1[2] + 1.0f);                                  \
            f3 = phi1.y * rcpa(d1[3] + 1.0f);                                  \
        }                                                                      \
    } while (0)

    // cheap step: read RA (hi frags), write WA (hi frags)
#define STEP_CHEAP(MH, RA, WA, ISBF)                                           \
    do {                                                                       \
        _Pragma("unroll")                                                      \
        for (int gg = 0; gg < 4; gg++) {                                       \
            uint4 hx = frag[(MH) * 512 +       (2*gg)   * 32];                 \
            uint4 hy = frag[(MH) * 512 +       (2*gg+1) * 32];                 \
            uint4 hz = frag[(MH) * 512 + 256 + (2*gg)   * 32];                 \
            uint4 hw = frag[(MH) * 512 + 256 + (2*gg+1) * 32];                 \
            float d0[4], d1[4];                                                \
            MMA_Z(d0, RA[0], hx.x, hx.y);                                      \
            MMA_Z(d1, RA[0], hy.x, hy.y);                                      \
            MMA(d0, RA[1], hx.z, hx.w);                                        \
            MMA(d1, RA[1], hy.z, hy.w);                                        \
            MMA(d0, RA[2], hz.x, hz.y);                                        \
            MMA(d1, RA[2], hw.x, hw.y);                                        \
            MMA(d0, RA[3], hz.z, hz.w);                                        \
            MMA(d1, RA[3], hw.z, hw.w);                                        \
            float e0,e1,e2,e3,f0,f1,f2,f3;                                     \
            GROUP_NONLIN(ISBF, gg, d0, d1, e0,e1,e2,e3, f0,f1,f2,f3);          \
            WA[gg][0] = packbf(e0, e1);                                        \
            WA[gg][1] = packbf(e2, e3);                                        \
            WA[gg][2] = packbf(f0, f1);                                        \
            WA[gg][3] = packbf(f2, f3);                                        \
        }                                                                      \
    } while (0)

    // full step: read (RAH,RAL), write (WAH,WAL); 3-term split MMAs
#define STEP_FULL(MH, RAH, RAL, WAH, WAL, ISBF)                                \
    do {                                                                       \
        _Pragma("unroll")                                                      \
        for (int gg = 0; gg < 4; gg++) {                                       \
            uint4 hx = frag[(MH) * 512 +       (2*gg)   * 32];                 \
            uint4 hy = frag[(MH) * 512 +       (2*gg+1) * 32];                 \
            uint4 hz = frag[(MH) * 512 + 256 + (2*gg)   * 32];                 \
            uint4 hw = frag[(MH) * 512 + 256 + (2*gg+1) * 32];                 \
            uint4 lx = frag[((MH)+1) * 512 +       (2*gg)   * 32];             \
            uint4 ly = frag[((MH)+1) * 512 +       (2*gg+1) * 32];             \
            uint4 lz = frag[((MH)+1) * 512 + 256 + (2*gg)   * 32];             \
            uint4 lw = frag[((MH)+1) * 512 + 256 + (2*gg+1) * 32];             \
            float d0[4], d1[4];                                                \
            MMA_Z(d0, RAH[0], hx.x, hx.y);                                     \
            MMA_Z(d1, RAH[0], hy.x, hy.y);                                     \
            MMA(d0, RAL[0], hx.x, hx.y);                                       \
            MMA(d1, RAL[0], hy.x, hy.y);                                       \
            MMA(d0, RAH[0], lx.x, lx.y);                                       \
            MMA(d1, RAH[0], ly.x, ly.y);                                       \
            MMA(d0, RAH[1], hx.z, hx.w);                                       \
            MMA(d1, RAH[1], hy.z, hy.w);                                       \
            MMA(d0, RAL[1], hx.z, hx.w);                                       \
            MMA(d1, RAL[1], hy.z, hy.w);                                       \
            MMA(d0, RAH[1], lx.z, lx.w);                                       \
            MMA(d1, RAH[1], ly.z, ly.w);                                       \
            MMA(d0, RAH[2], hz.x, hz.y);                                       \
            MMA(d1, RAH[2], hw.x, hw.y);                                       \
            MMA(d0, RAL[2], hz.x, hz.y);                                       \
            MMA(d1, RAL[2], hw.x, hw.y);                                       \
            MMA(d0, RAH[2], lz.x, lz.y);                                       \
            MMA(d1, RAH[2], lw.x, lw.y);                                       \
            MMA(d0, RAH[3], hz.z, hz.w);                                       \
            MMA(d1, RAH[3], hw.z, hw.w);                                       \
            MMA(d0, RAL[3], hz.z, hz.w);                                       \
            MMA(d1, RAL[3], hw.z, hw.w);                                       \
            MMA(d0, RAH[3], lz.z, lz.w);                                       \
            MMA(d1, RAH[3], lw.z, lw.w);                                       \
            float e0,e1,e2,e3,f0,f1,f2,f3;                                     \
            GROUP_NONLIN(ISBF, gg, d0, d1, e0,e1,e2,e3, f0,f1,f2,f3);          \
            split2(e0, e1, WAH[gg][0], WAL[gg][0]);                            \
            split2(e2, e3, WAH[gg][1], WAL[gg][1]);                            \
            split2(f0, f1, WAH[gg][2], WAL[gg][2]);                            \
            split2(f2, f3, WAH[gg][3], WAL[gg][3]);                            \
        }                                                                      \
    } while (0)

    // all-D full phase (for final BF step + epilogue): fills d[8][4]
#define MMA_PHASE_FULL_ALLD(MH, RAH, RAL, D)                                   \
    do {                                                                       \
        _Pragma("unroll")                                                      \
        for (int sel = 0; sel < 2; sel++) {                                    \
            _Pragma("unroll")                                                  \
            for (int nt = 0; nt < 8; nt++) {                                   \
                uint4 h = frag[(MH) * 512 + sel * 256 + nt * 32];              \
                uint4 l = frag[((MH)+1) * 512 + sel * 256 + nt * 32];          \
                if (sel == 0) {                                                \
                    MMA_Z(D[nt], RAH[0], h.x, h.y);                            \
                } else {                                                       \
                    MMA(D[nt], RAH[2], h.x, h.y);                              \
                }                                                              \
                MMA(D[nt], RAL[2*sel],   h.x, h.y);                            \
                MMA(D[nt], RAH[2*sel],   l.x, l.y);                            \
                MMA(D[nt], RAH[2*sel+1], h.z, h.w);                            \
                MMA(D[nt], RAL[2*sel+1], h.z, h.w);                            \
                MMA(D[nt], RAH[2*sel+1], l.z, l.w);                            \
            }                                                                  \
        }                                                                      \
    } while (0)

    // ---- phase 1: 14 cheap iterations (hi-only), ping-pong ahA <-> ahB -----
    #pragma unroll 1
    for (int it = 0; it < CHEAP_ITERS; ++it) {
        STEP_CHEAP(0, ahA, ahB, 1);   // BF-step: reads AF(ahA), writes BF(ahB)
        STEP_CHEAP(2, ahB, ahA, 0);   // AF-step: reads BF(ahB), writes AF(ahA)
    }

    // precision boundary: lo residuals start at zero
    #pragma unroll
    for (int kt = 0; kt < 4; kt++)
        #pragma unroll
        for (int r = 0; r < 4; r++) { alA[kt][r] = 0u; }

    // ---- phase 2: 3 precise BF/AF pairs, then final BF (all-D) -------------
    #pragma unroll 1
    for (int it = 0; it < 3; ++it) {
        STEP_FULL(0, ahA, alA, ahB, alB, 1);   // BF
        STEP_FULL(2, ahB, alB, ahA, alA, 0);   // AF
    }

    // final BF step: keep fp32 D (final BF) for the output contraction
    float d[8][4];
    MMA_PHASE_FULL_ALLD(0, ahA, alA, d);
    #pragma unroll
    for (int nt = 0; nt < 8; nt++) {
        d[nt][0] = btv[2*nt+0] * rcpa(d[nt][0] + 1.0f);
        d[nt][1] = btv[2*nt+1] * rcpa(d[nt][1] + 1.0f);
        d[nt][2] = btv[2*nt+0] * rcpa(d[nt][2] + 1.0f);
        d[nt][3] = btv[2*nt+1] * rcpa(d[nt][3] + 1.0f);
    }

    // stash final BF (fp32) into the AT region (AT is dead; same-lane rw)
    #pragma unroll
    for (int nt = 0; nt < 8; nt++) {
        int cb = 8 * nt + 2 * t;
        *reinterpret_cast<float2*>(ats + rlo + cb) =
            make_float2(d[nt][0], d[nt][1]);
        *reinterpret_cast<float2*>(ats + rhi + cb) =
            make_float2(d[nt][2], d[nt][3]);
    }

    // epilogue: H = AF @ M (ahA/alA hold final AF); y = sum BF * H
    MMA_PHASE_FULL_ALLD(4, ahA, alA, d);

    float y0 = 0.f, y1 = 0.f;
    #pragma unroll
    for (int nt = 0; nt < 8; nt++) {
        int cb = 8 * nt + 2 * t;
        float2 blo = *reinterpret_cast<const float2*>(ats + rlo + cb);
        float2 bhi = *reinterpret_cast<const float2*>(ats + rhi + cb);
        y0 = fmaf(blo.x, d[nt][0], fmaf(blo.y, d[nt][1], y0));
        y1 = fmaf(bhi.x, d[nt][2], fmaf(bhi.y, d[nt][3], y1));
    }

    y0 += __shfl_xor_sync(0xFFFFFFFFu, y0, 1);
    y0 += __shfl_xor_sync(0xFFFFFFFFu, y0, 2);
    y1 += __shfl_xor_sync(0xFFFFFFFFu, y1, 1);
    y1 += __shfl_xor_sync(0xFFFFFFFFu, y1, 2);

    if (t == 0) {
        float bc = fminf(fmaxf(braw[0], -10.0f), 10.0f);
        size_t base = (size_t)bid * ROWS_PER_CTA + rb + g;
        out[base + 0] = y0 + bc;
        out[base + 8] = y1 + bc;
    }
}

extern "C" void kernel_launch(void* const* d_in, const int* in_sizes, int n_in,
                              void* d_out, int out_size)
{
    const float* AT    = (const float*)d_in[0];
    const float* Kraw  = (const float*)d_in[1];
    const float* BTraw = (const float*)d_in[2];
    const float* Wraw  = (const float*)d_in[3];
    const float* braw  = (const float*)d_in[4];
    float* out = (float*)d_out;

    const int B = in_sizes[0] / N_DIM;          // 16384
    const int grid = B / ROWS_PER_CTA;          // 128

    cudaFuncSetAttribute(cnet_mma_kernel,
                         cudaFuncAttributeMaxDynamicSharedMemorySize,
                         SMEM_TOTAL);

    cnet_mma_kernel<<<grid, THREADS, SMEM_TOTAL>>>(
        AT, Kraw, BTraw, Wraw, braw, out);
}

// round 10
// speedup vs baseline: 1.2886x; 1.0921x over previous
#include <cuda_runtime.h>
#include <cuda_bf16.h>
#include <cstdint>
#include <cstddef>

// CompetitiveNetwork via mma.sync (m16n8k16 bf16, fp32 accum).
// R9: pure instruction-elimination on the R6 skeleton.
//  (1) +1.0 folded into MMA accumulator init (C={1,1,1,1} on the first HMMA
//      of each accumulator) -> d = S+1 straight from tensor pipe.
//  (2) BT folded into B matrices: BF state is BF' = rcp(S+1); bt_j scales the
//      AF-step matrix (K*bt_j) and epilogue matrix (K.W*bt_j) columns. btv
//      registers deleted.
//  (3) In-place repack (no ping-pong A buffers) -> -32 regs.
// 8 warps/CTA, 16 rows/warp, state in registers, no syncs in the loop.
// 14 cheap (hi-only) + 4 precise (3-term split) iterations.

#define THREADS 256
#define ROWS_PER_CTA 128
#define N_DIM 64
#define CHEAP_ITERS 14

typedef unsigned int u32;

#define MATS_BYTES (6 * 8192)              // fragment-ordered split matrices
#define AT_OFF     MATS_BYTES
#define AT_STRIDE  66
#define SMEM_TOTAL (AT_OFF + 128 * AT_STRIDE * 4)   // 82944

__device__ __forceinline__ float rcpa(float x) {
    float r; asm("rcp.approx.f32 %0, %1;" : "=f"(r) : "f"(x)); return r;
}
__device__ __forceinline__ u32 packbf(float lo_elem, float hi_elem) {
    u32 r; asm("cvt.rn.bf16x2.f32 %0, %1, %2;" : "=r"(r)
               : "f"(hi_elem), "f"(lo_elem));
    return r;
}
__device__ __forceinline__ void split2(float x0, float x1, u32 &hi, u32 &lo) {
    hi = packbf(x0, x1);
    float h0 = __uint_as_float(hi << 16);
    float h1 = __uint_as_float(hi & 0xFFFF0000u);
    lo = packbf(x0 - h0, x1 - h1);
}

// fragment-order store: element at logical (k, n) of a B operand
__device__ __forceinline__ void st_frag(__nv_bfloat16* base, int k, int n,
                                        __nv_bfloat16 v) {
    int lane = ((n & 7) << 2) | ((k & 7) >> 1);
    int w2   = (((k >> 4) & 1) << 1) | ((k >> 3) & 1);
    int idx  = ((k >> 5) << 11) | ((n >> 3) << 8) | (lane << 3)
             | (w2 << 1) | (k & 1);
    base[idx] = v;
}

#define MMA(d, a, b0, b1)                                                      \
    asm("mma.sync.aligned.m16n8k16.row.col.f32.bf16.bf16.f32 "                 \
        "{%0,%1,%2,%3}, {%4,%5,%6,%7}, {%8,%9}, {%0,%1,%2,%3};"                \
        : "+f"((d)[0]), "+f"((d)[1]), "+f"((d)[2]), "+f"((d)[3])               \
        : "r"((a)[0]), "r"((a)[1]), "r"((a)[2]), "r"((a)[3]),                  \
          "r"(b0), "r"(b1))

// first MMA of an accumulator, C = 0 (epilogue H: no bias)
#define MMA_Z(d, a, b0, b1)                                                    \
    asm("mma.sync.aligned.m16n8k16.row.col.f32.bf16.bf16.f32 "                 \
        "{%0,%1,%2,%3}, {%4,%5,%6,%7}, {%8,%9}, {%10,%10,%10,%10};"            \
        : "=f"((d)[0]), "=f"((d)[1]), "=f"((d)[2]), "=f"((d)[3])               \
        : "r"((a)[0]), "r"((a)[1]), "r"((a)[2]), "r"((a)[3]),                  \
          "r"(b0), "r"(b1), "f"(0.0f))

// first MMA of an accumulator, C = 1 (folds the "+1.0" of the nonlinearity)
#define MMA_ONE(d, a, b0, b1)                                                  \
    asm("mma.sync.aligned.m16n8k16.row.col.f32.bf16.bf16.f32 "                 \
        "{%0,%1,%2,%3}, {%4,%5,%6,%7}, {%8,%9}, {%10,%10,%10,%10};"            \
        : "=f"((d)[0]), "=f"((d)[1]), "=f"((d)[2]), "=f"((d)[3])               \
        : "r"((a)[0]), "r"((a)[1]), "r"((a)[2]), "r"((a)[3]),                  \
          "r"(b0), "r"(b1), "f"(1.0f))

__global__ void __launch_bounds__(THREADS, 1)
cnet_mma_kernel(const float* __restrict__ AT,
                const float* __restrict__ Kraw,
                const float* __restrict__ BTraw,
                const float* __restrict__ Wraw,
                const float* __restrict__ braw,
                float* __restrict__ out)
{
    extern __shared__ char smc[];
    __nv_bfloat16* mats = reinterpret_cast<__nv_bfloat16*>(smc);
    float* ats = reinterpret_cast<float*>(smc + AT_OFF);   // [128][66] f32

    const int tid  = threadIdx.x;
    const int w    = tid >> 5;          // warp 0..7 -> rows [16w, 16w+16)
    const int lane = tid & 31;
    const int g    = lane >> 2;
    const int t    = lane & 3;
    const int rb   = w * 16;
    const int bid  = blockIdx.x;

    // ---- setup: exp/clip K, bt-folded fragment-ordered split matrices ------
    // mats 0/1: KT hi/lo        B(k=i,n=j) = K[i][j]          (BF-step)
    // mats 2/3: K'  hi/lo       B(k=j,n=i) = K[i][j]*bt[j]    (AF-step)
    // mats 4/5: M'  hi/lo       B(k=i,n=j) = K[i][j]*W*bt[j]  (epilogue)
    for (int idx = tid; idx < 4096; idx += THREADS) {
        int i = idx >> 6, j = idx & 63;
        float k = fminf(__expf(Kraw[idx]), 1000.0f);
        float btj = fminf(__expf(BTraw[j]), 1000.0f);
        float wv = fminf(fmaxf(Wraw[idx], -10.0f), 10.0f);
        float kp = k * btj;           // AF-step matrix
        float m  = k * wv * btj;      // epilogue matrix
        __nv_bfloat16 kh = __float2bfloat16_rn(k);
        __nv_bfloat16 kl = __float2bfloat16_rn(k - __bfloat162float(kh));
        __nv_bfloat16 ph = __float2bfloat16_rn(kp);
        __nv_bfloat16 pl = __float2bfloat16_rn(kp - __bfloat162float(ph));
        __nv_bfloat16 mh = __float2bfloat16_rn(m);
        __nv_bfloat16 ml = __float2bfloat16_rn(m - __bfloat162float(mh));
        st_frag(mats + 0 * 4096, i, j, kh);
        st_frag(mats + 1 * 4096, i, j, kl);
        st_frag(mats + 2 * 4096, j, i, ph);
        st_frag(mats + 3 * 4096, j, i, pl);
        st_frag(mats + 4 * 4096, i, j, mh);
        st_frag(mats + 5 * 4096, i, j, ml);
    }
    {
        const float4* atg = reinterpret_cast<const float4*>(
            AT + (size_t)bid * (ROWS_PER_CTA * N_DIM));
        for (int idx = tid; idx < 2048; idx += THREADS) {
            float4 v = atg[idx];
            int r = idx >> 4, c = (idx & 15) << 2;
            float* p = ats + r * AT_STRIDE + c;
            p[0] = v.x; p[1] = v.y; p[2] = v.z; p[3] = v.w;
        }
    }
    __syncthreads();

    const int rlo = (rb + g) * AT_STRIDE;
    const int rhi = (rb + 8 + g) * AT_STRIDE;

    // ---- fragment registers --------------------------------------------------
    float d[8][4];            // D frags: [nt][c]
    u32 ah[4][4], al[4][4];   // A frags hi/lo

    // initial A = bf16(AT) (hi only; lo joins at the precision boundary)
    #pragma unroll
    for (int kt = 0; kt < 4; kt++) {
        int cb = 16 * kt + 2 * t;
        float2 p0 = *reinterpret_cast<const float2*>(ats + rlo + cb);
        float2 p1 = *reinterpret_cast<const float2*>(ats + rhi + cb);
        float2 p2 = *reinterpret_cast<const float2*>(ats + rlo + cb + 8);
        float2 p3 = *reinterpret_cast<const float2*>(ats + rhi + cb + 8);
        ah[kt][0] = packbf(p0.x, p0.y);
        ah[kt][1] = packbf(p1.x, p1.y);
        ah[kt][2] = packbf(p2.x, p2.y);
        ah[kt][3] = packbf(p3.x, p3.y);
    }

    const uint4* __restrict__ frag = reinterpret_cast<const uint4*>(smc) + lane;

    // cheap matvec: d = A_hi @ B_hi + 1
#define MMA_PHASE_CHEAP(MH)                                                    \
    do {                                                                       \
        _Pragma("unroll")                                                      \
        for (int nt = 0; nt < 8; nt++) {                                       \
            uint4 h0 = frag[(MH) * 512 +       nt * 32];                       \
            uint4 h1 = frag[(MH) * 512 + 256 + nt * 32];                       \
            MMA_ONE(d[nt], ah[0], h0.x, h0.y);                                 \
            MMA(d[nt], ah[1], h0.z, h0.w);                                     \
            MMA(d[nt], ah[2], h1.x, h1.y);                                     \
            MMA(d[nt], ah[3], h1.z, h1.w);                                     \
        }                                                                      \
    } while (0)

    // full matvec: d = (Ah+Al) @ Bh + Ah @ Bl + BIAS (BIAS = MMA_ONE/MMA_Z)
#define MMA_PHASE_FULL(MH, FIRST)                                              \
    do {                                                                       \
        _Pragma("unroll")                                                      \
        for (int nt = 0; nt < 8; nt++) {                                       \
            uint4 h0 = frag[(MH) * 512 +       nt * 32];                       \
            uint4 h1 = frag[(MH) * 512 + 256 + nt * 32];                       \
            uint4 l0 = frag[((MH)+1) * 512 +       nt * 32];                   \
            uint4 l1 = frag[((MH)+1) * 512 + 256 + nt * 32];                   \
            FIRST(d[nt], ah[0], h0.x, h0.y);                                   \
            MMA(d[nt], al[0], h0.x, h0.y);                                     \
            MMA(d[nt], ah[0], l0.x, l0.y);                                     \
            MMA(d[nt], ah[1], h0.z, h0.w);                                     \
            MMA(d[nt], al[1], h0.z, h0.w);                                     \
            MMA(d[nt], ah[1], l0.z, l0.w);                                     \
            MMA(d[nt], ah[2], h1.x, h1.y);                                     \
            MMA(d[nt], al[2], h1.x, h1.y);                                     \
            MMA(d[nt], ah[2], l1.x, l1.y);                                     \
            MMA(d[nt], ah[3], h1.z, h1.w);                                     \
            MMA(d[nt], al[3], h1.z, h1.w);                                     \
            MMA(d[nt], ah[3], l1.z, l1.w);                                     \
        }                                                                      \
    } while (0)

    // BF' nonlinearity: d = rcp(d)   (bt folded into next matrix)
#define BF_NONLIN()                                                            \
    do {                                                                       \
        _Pragma("unroll")                                                      \
        for (int nt = 0; nt < 8; nt++) {                                       \
            d[nt][0] = rcpa(d[nt][0]);                                         \
            d[nt][1] = rcpa(d[nt][1]);                                         \
            d[nt][2] = rcpa(d[nt][2]);                                         \
            d[nt][3] = rcpa(d[nt][3]);                                         \
        }                                                                      \
    } while (0)

    // AF nonlinearity: d = AT * rcp(d)
#define AF_NONLIN()                                                            \
    do {                                                                       \
        _Pragma("unroll")                                                      \
        for (int nt = 0; nt < 8; nt++) {                                       \
            int cb = 8 * nt + 2 * t;                                           \
            float2 plo = *reinterpret_cast<const float2*>(ats + rlo + cb);     \
            float2 phi = *reinterpret_cast<const float2*>(ats + rhi + cb);     \
            d[nt][0] = plo.x * rcpa(d[nt][0]);                                 \
            d[nt][1] = plo.y * rcpa(d[nt][1]);                                 \
            d[nt][2] = phi.x * rcpa(d[nt][2]);                                 \
            d[nt][3] = phi.y * rcpa(d[nt][3]);                                 \
        }                                                                      \
    } while (0)

    // cheap repack: d -> ah only (in place; d fully computed first)
#define REPACK_CHEAP()                                                         \
    do {                                                                       \
        _Pragma("unroll")                                                      \
        for (int kt = 0; kt < 4; kt++) {                                       \
            ah[kt][0] = packbf(d[2*kt][0],   d[2*kt][1]);                      \
            ah[kt][1] = packbf(d[2*kt][2],   d[2*kt][3]);                      \
            ah[kt][2] = packbf(d[2*kt+1][0], d[2*kt+1][1]);                    \
            ah[kt][3] = packbf(d[2*kt+1][2], d[2*kt+1][3]);                    \
        }                                                                      \
    } while (0)

    // full repack: d -> (ah, al)
#define REPACK_FULL()                                                          \
    do {                                                                       \
        _Pragma("unroll")                                                      \
        for (int kt = 0; kt < 4; kt++) {                                       \
            split2(d[2*kt][0],   d[2*kt][1],   ah[kt][0], al[kt][0]);          \
            split2(d[2*kt][2],   d[2*kt][3],   ah[kt][1], al[kt][1]);          \
            split2(d[2*kt+1][0], d[2*kt+1][1], ah[kt][2], al[kt][2]);          \
            split2(d[2*kt+1][2], d[2*kt+1][3], ah[kt][3], al[kt][3]);          \
        }                                                                      \
    } while (0)

    // ---- phase 1: 14 cheap iterations (hi-only) -----------------------------
    #pragma unroll 1
    for (int it = 0; it < CHEAP_ITERS; ++it) {
        MMA_PHASE_CHEAP(0);   // BF-step: d = KT^T(AF) + 1
        BF_NONLIN();          // BF' = rcp(d)
        REPACK_CHEAP();
        MMA_PHASE_CHEAP(2);   // AF-step: d = K'(BF') + 1
        AF_NONLIN();          // AF = AT * rcp(d)
        REPACK_CHEAP();
    }

    // precision boundary: lo residuals start at zero
    #pragma unroll
    for (int kt = 0; kt < 4; kt++)
        #pragma unroll
        for (int r = 0; r < 4; r++) al[kt][r] = 0u;

    // ---- phase 2: 3 precise BF/AF pairs, then final BF ----------------------
    #pragma unroll 1
    for (int it = 0; it < 3; ++it) {
        MMA_PHASE_FULL(0, MMA_ONE);
        BF_NONLIN();
        REPACK_FULL();
        MMA_PHASE_FULL(2, MMA_ONE);
        AF_NONLIN();
        REPACK_FULL();
    }

    // final BF step: keep fp32 BF' for the output contraction
    MMA_PHASE_FULL(0, MMA_ONE);
    BF_NONLIN();

    // stash final BF' (fp32) into the AT region (AT dead; same-lane rw)
    #pragma unroll
    for (int nt = 0; nt < 8; nt++) {
        int cb = 8 * nt + 2 * t;
        *reinterpret_cast<float2*>(ats + rlo + cb) =
            make_float2(d[nt][0], d[nt][1]);
        *reinterpret_cast<float2*>(ats + rhi + cb) =
            make_float2(d[nt][2], d[nt][3]);
    }

    // epilogue: H = AF @ M' (C = 0); y = sum_j BF'_j H_j
    MMA_PHASE_FULL(4, MMA_Z);

    float y0 = 0.f, y1 = 0.f;
    #pragma unroll
    for (int nt = 0; nt < 8; nt++) {
        int cb = 8 * nt + 2 * t;
        float2 blo = *reinterpret_cast<const float2*>(ats + rlo + cb);
        float2 bhi = *reinterpret_cast<const float2*>(ats + rhi + cb);
        y0 = fmaf(blo.x, d[nt][0], fmaf(blo.y, d[nt][1], y0));
        y1 = fmaf(bhi.x, d[nt][2], fmaf(bhi.y, d[nt][3], y1));
    }

    y0 += __shfl_xor_sync(0xFFFFFFFFu, y0, 1);
    y0 += __shfl_xor_sync(0xFFFFFFFFu, y0, 2);
    y1 += __shfl_xor_sync(0xFFFFFFFFu, y1, 1);
    y1 += __shfl_xor_sync(0xFFFFFFFFu, y1, 2);

    if (t == 0) {
        float bc = fminf(fmaxf(braw[0], -10.0f), 10.0f);
        size_t base = (size_t)bid * ROWS_PER_CTA + rb + g;
        out[base + 0] = y0 + bc;
        out[base + 8] = y1 + bc;
    }
}

extern "C" void kernel_launch(void* const* d_in, const int* in_sizes, int n_in,
                              void* d_out, int out_size)
{
    const float* AT    = (const float*)d_in[0];
    const float* Kraw  = (const float*)d_in[1];
    const float* BTraw = (const float*)d_in[2];
    const float* Wraw  = (const float*)d_in[3];
    const float* braw  = (const float*)d_in[4];
    float* out = (float*)d_out;

    const int B = in_sizes[0] / N_DIM;          // 16384
    const int grid = B / ROWS_PER_CTA;          // 128

    cudaFuncSetAttribute(cnet_mma_kernel,
                         cudaFuncAttributeMaxDynamicSharedMemorySize,
                         SMEM_TOTAL);

    cnet_mma_kernel<<<grid, THREADS, SMEM_TOTAL>>>(
        AT, Kraw, BTraw, Wraw, braw, out);
}

// round 11
// speedup vs baseline: 1.2955x; 1.0054x over previous
#include <cuda_runtime.h>
#include <cuda_bf16.h>
#include <cstdint>
#include <cstddef>

// CompetitiveNetwork via mma.sync (m16n8k16 bf16, fp32 accum).
// R10: register-hoist the loop-invariant B fragments. The cheap phase's two
// hi matrices (KT-hi, K'-hi) are 32 uint4 = 128 regs of per-thread fragments,
// constant across all 14 iterations -> hold them in registers; all LDS and
// address arithmetic leave the cheap loop. Precise phase reuses the same hi
// fragment registers (only lo matrices load). AT cached in 32 regs.
// Loop body = pure HMMA + MUFU + CVT. Everything else as R9 (bt folded into
// matrices, +1 folded into accumulator init, 14 cheap + 4 precise).

#define THREADS 256
#define ROWS_PER_CTA 128
#define N_DIM 64
#define CHEAP_ITERS 14

typedef unsigned int u32;

#define MATS_BYTES (6 * 8192)              // fragment-ordered split matrices
#define AT_OFF     MATS_BYTES
#define AT_STRIDE  66
#define SMEM_TOTAL (AT_OFF + 128 * AT_STRIDE * 4)   // 82944

__device__ __forceinline__ float rcpa(float x) {
    float r; asm("rcp.approx.f32 %0, %1;" : "=f"(r) : "f"(x)); return r;
}
__device__ __forceinline__ u32 packbf(float lo_elem, float hi_elem) {
    u32 r; asm("cvt.rn.bf16x2.f32 %0, %1, %2;" : "=r"(r)
               : "f"(hi_elem), "f"(lo_elem));
    return r;
}
__device__ __forceinline__ void split2(float x0, float x1, u32 &hi, u32 &lo) {
    hi = packbf(x0, x1);
    float h0 = __uint_as_float(hi << 16);
    float h1 = __uint_as_float(hi & 0xFFFF0000u);
    lo = packbf(x0 - h0, x1 - h1);
}

// fragment-order store: element at logical (k, n) of a B operand
__device__ __forceinline__ void st_frag(__nv_bfloat16* base, int k, int n,
                                        __nv_bfloat16 v) {
    int lane = ((n & 7) << 2) | ((k & 7) >> 1);
    int w2   = (((k >> 4) & 1) << 1) | ((k >> 3) & 1);
    int idx  = ((k >> 5) << 11) | ((n >> 3) << 8) | (lane << 3)
             | (w2 << 1) | (k & 1);
    base[idx] = v;
}

#define MMA(d, a, b0, b1)                                                      \
    asm("mma.sync.aligned.m16n8k16.row.col.f32.bf16.bf16.f32 "                 \
        "{%0,%1,%2,%3}, {%4,%5,%6,%7}, {%8,%9}, {%0,%1,%2,%3};"                \
        : "+f"((d)[0]), "+f"((d)[1]), "+f"((d)[2]), "+f"((d)[3])               \
        : "r"((a)[0]), "r"((a)[1]), "r"((a)[2]), "r"((a)[3]),                  \
          "r"(b0), "r"(b1))

#define MMA_Z(d, a, b0, b1)                                                    \
    asm("mma.sync.aligned.m16n8k16.row.col.f32.bf16.bf16.f32 "                 \
        "{%0,%1,%2,%3}, {%4,%5,%6,%7}, {%8,%9}, {%10,%10,%10,%10};"            \
        : "=f"((d)[0]), "=f"((d)[1]), "=f"((d)[2]), "=f"((d)[3])               \
        : "r"((a)[0]), "r"((a)[1]), "r"((a)[2]), "r"((a)[3]),                  \
          "r"(b0), "r"(b1), "f"(0.0f))

#define MMA_ONE(d, a, b0, b1)                                                  \
    asm("mma.sync.aligned.m16n8k16.row.col.f32.bf16.bf16.f32 "                 \
        "{%0,%1,%2,%3}, {%4,%5,%6,%7}, {%8,%9}, {%10,%10,%10,%10};"            \
        : "=f"((d)[0]), "=f"((d)[1]), "=f"((d)[2]), "=f"((d)[3])               \
        : "r"((a)[0]), "r"((a)[1]), "r"((a)[2]), "r"((a)[3]),                  \
          "r"(b0), "r"(b1), "f"(1.0f))

__global__ void __launch_bounds__(THREADS, 1)
cnet_mma_kernel(const float* __restrict__ AT,
                const float* __restrict__ Kraw,
                const float* __restrict__ BTraw,
                const float* __restrict__ Wraw,
                const float* __restrict__ braw,
                float* __restrict__ out)
{
    extern __shared__ char smc[];
    __nv_bfloat16* mats = reinterpret_cast<__nv_bfloat16*>(smc);
    float* ats = reinterpret_cast<float*>(smc + AT_OFF);   // [128][66] f32

    const int tid  = threadIdx.x;
    const int w    = tid >> 5;          // warp 0..7 -> rows [16w, 16w+16)
    const int lane = tid & 31;
    const int g    = lane >> 2;
    const int t    = lane & 3;
    const int rb   = w * 16;
    const int bid  = blockIdx.x;

    // ---- setup: exp/clip K, bt-folded fragment-ordered split matrices ------
    // mats 0/1: KT hi/lo   B(k=i,n=j) = K[i][j]           (BF-step)
    // mats 2/3: K'  hi/lo  B(k=j,n=i) = K[i][j]*bt[j]     (AF-step)
    // mats 4/5: M'  hi/lo  B(k=i,n=j) = K[i][j]*W*bt[j]   (epilogue)
    for (int idx = tid; idx < 4096; idx += THREADS) {
        int i = idx >> 6, j = idx & 63;
        float k = fminf(__expf(Kraw[idx]), 1000.0f);
        float btj = fminf(__expf(BTraw[j]), 1000.0f);
        float wv = fminf(fmaxf(Wraw[idx], -10.0f), 10.0f);
        float kp = k * btj;
        float m  = k * wv * btj;
        __nv_bfloat16 kh = __float2bfloat16_rn(k);
        __nv_bfloat16 kl = __float2bfloat16_rn(k - __bfloat162float(kh));
        __nv_bfloat16 ph = __float2bfloat16_rn(kp);
        __nv_bfloat16 pl = __float2bfloat16_rn(kp - __bfloat162float(ph));
        __nv_bfloat16 mh = __float2bfloat16_rn(m);
        __nv_bfloat16 ml = __float2bfloat16_rn(m - __bfloat162float(mh));
        st_frag(mats + 0 * 4096, i, j, kh);
        st_frag(mats + 1 * 4096, i, j, kl);
        st_frag(mats + 2 * 4096, j, i, ph);
        st_frag(mats + 3 * 4096, j, i, pl);
        st_frag(mats + 4 * 4096, i, j, mh);
        st_frag(mats + 5 * 4096, i, j, ml);
    }
    {
        const float4* atg = reinterpret_cast<const float4*>(
            AT + (size_t)bid * (ROWS_PER_CTA * N_DIM));
        for (int idx = tid; idx < 2048; idx += THREADS) {
            float4 v = atg[idx];
            int r = idx >> 4, c = (idx & 15) << 2;
            float* p = ats + r * AT_STRIDE + c;
            p[0] = v.x; p[1] = v.y; p[2] = v.z; p[3] = v.w;
        }
    }
    __syncthreads();

    const int rlo = (rb + g) * AT_STRIDE;
    const int rhi = (rb + 8 + g) * AT_STRIDE;

    const uint4* __restrict__ frag = reinterpret_cast<const uint4*>(smc) + lane;

    // ---- register-resident loop-invariant hi fragments ----------------------
    // b0 = KT-hi (BF-step), b2 = K'-hi (AF-step): [2*nt] = sel0, [2*nt+1] = sel1
    uint4 b0[16], b2[16];
    #pragma unroll
    for (int nt = 0; nt < 8; nt++) {
        b0[2*nt]   = frag[0 * 512 +       nt * 32];
        b0[2*nt+1] = frag[0 * 512 + 256 + nt * 32];
        b2[2*nt]   = frag[2 * 512 +       nt * 32];
        b2[2*nt+1] = frag[2 * 512 + 256 + nt * 32];
    }

    // AT cached in registers (consumed by AF_NONLIN every AF-step)
    float atc[8][4];
    #pragma unroll
    for (int nt = 0; nt < 8; nt++) {
        int cb = 8 * nt + 2 * t;
        float2 plo = *reinterpret_cast<const float2*>(ats + rlo + cb);
        float2 phi = *reinterpret_cast<const float2*>(ats + rhi + cb);
        atc[nt][0] = plo.x; atc[nt][1] = plo.y;
        atc[nt][2] = phi.x; atc[nt][3] = phi.y;
    }

    // ---- fragment registers --------------------------------------------------
    float d[8][4];
    u32 ah[4][4], al[4][4];

    // initial A = bf16(AT)
    #pragma unroll
    for (int kt = 0; kt < 4; kt++) {
        int cb = 16 * kt + 2 * t;
        float2 p0 = *reinterpret_cast<const float2*>(ats + rlo + cb);
        float2 p1 = *reinterpret_cast<const float2*>(ats + rhi + cb);
        float2 p2 = *reinterpret_cast<const float2*>(ats + rlo + cb + 8);
        float2 p3 = *reinterpret_cast<const float2*>(ats + rhi + cb + 8);
        ah[kt][0] = packbf(p0.x, p0.y);
        ah[kt][1] = packbf(p1.x, p1.y);
        ah[kt][2] = packbf(p2.x, p2.y);
        ah[kt][3] = packbf(p3.x, p3.y);
    }

    // cheap matvec from register fragments: d = A_hi @ B_hi + 1
#define MMA_PHASE_CHEAP_R(B)                                                   \
    do {                                                                       \
        _Pragma("unroll")                                                      \
        for (int nt = 0; nt < 8; nt++) {                                       \
            MMA_ONE(d[nt], ah[0], B[2*nt].x,   B[2*nt].y);                     \
            MMA(d[nt], ah[1], B[2*nt].z,   B[2*nt].w);                         \
            MMA(d[nt], ah[2], B[2*nt+1].x, B[2*nt+1].y);                       \
            MMA(d[nt], ah[3], B[2*nt+1].z, B[2*nt+1].w);                       \
        }                                                                      \
    } while (0)

    // full matvec: hi from registers (BH), lo loaded from mats[ML]
#define MMA_PHASE_FULL_R(BH, ML, FIRST)                                        \
    do {                                                                       \
        _Pragma("unroll")                                                      \
        for (int nt = 0; nt < 8; nt++) {                                       \
            uint4 l0 = frag[(ML) * 512 +       nt * 32];                       \
            uint4 l1 = frag[(ML) * 512 + 256 + nt * 32];                       \
            FIRST(d[nt], ah[0], BH[2*nt].x, BH[2*nt].y);                       \
            MMA(d[nt], al[0], BH[2*nt].x, BH[2*nt].y);                         \
            MMA(d[nt], ah[0], l0.x, l0.y);                                     \
            MMA(d[nt], ah[1], BH[2*nt].z, BH[2*nt].w);                         \
            MMA(d[nt], al[1], BH[2*nt].z, BH[2*nt].w);                         \
            MMA(d[nt], ah[1], l0.z, l0.w);                                     \
            MMA(d[nt], ah[2], BH[2*nt+1].x, BH[2*nt+1].y);                     \
            MMA(d[nt], al[2], BH[2*nt+1].x, BH[2*nt+1].y);                     \
            MMA(d[nt], ah[2], l1.x, l1.y);                                     \
            MMA(d[nt], ah[3], BH[2*nt+1].z, BH[2*nt+1].w);                     \
            MMA(d[nt], al[3], BH[2*nt+1].z, BH[2*nt+1].w);                     \
            MMA(d[nt], ah[3], l1.z, l1.w);                                     \
        }                                                                      \
    } while (0)

    // full matvec entirely from memory (epilogue mats 4/5)
#define MMA_PHASE_FULL_MEM(MH, FIRST)                                          \
    do {                                                                       \
        _Pragma("unroll")                                                      \
        for (int nt = 0; nt < 8; nt++) {                                       \
            uint4 h0 = frag[(MH) * 512 +       nt * 32];                       \
            uint4 h1 = frag[(MH) * 512 + 256 + nt * 32];                       \
            uint4 l0 = frag[((MH)+1) * 512 +       nt * 32];                   \
            uint4 l1 = frag[((MH)+1) * 512 + 256 + nt * 32];                   \
            FIRST(d[nt], ah[0], h0.x, h0.y);                                   \
            MMA(d[nt], al[0], h0.x, h0.y);                                     \
            MMA(d[nt], ah[0], l0.x, l0.y);                                     \
            MMA(d[nt], ah[1], h0.z, h0.w);                                     \
            MMA(d[nt], al[1], h0.z, h0.w);                                     \
            MMA(d[nt], ah[1], l0.z, l0.w);                                     \
            MMA(d[nt], ah[2], h1.x, h1.y);                                     \
            MMA(d[nt], al[2], h1.x, h1.y);                                     \
            MMA(d[nt], ah[2], l1.x, l1.y);                                     \
            MMA(d[nt], ah[3], h1.z, h1.w);                                     \
            MMA(d[nt], al[3], h1.z, h1.w);                                     \
            MMA(d[nt], ah[3], l1.z, l1.w);                                     \
        }                                                                      \
    } while (0)

#define BF_NONLIN()                                                            \
    do {                                                                       \
        _Pragma("unroll")                                                      \
        for (int nt = 0; nt < 8; nt++) {                                       \
            d[nt][0] = rcpa(d[nt][0]);                                         \
            d[nt][1] = rcpa(d[nt][1]);                                         \
            d[nt][2] = rcpa(d[nt][2]);                                         \
            d[nt][3] = rcpa(d[nt][3]);                                         \
        }                                                                      \
    } while (0)

#define AF_NONLIN()                                                            \
    do {                                                                       \
        _Pragma("unroll")                                                      \
        for (int nt = 0; nt < 8; nt++) {                                       \
            d[nt][0] = atc[nt][0] * rcpa(d[nt][0]);                            \
            d[nt][1] = atc[nt][1] * rcpa(d[nt][1]);                            \
            d[nt][2] = atc[nt][2] * rcpa(d[nt][2]);                            \
            d[nt][3] = atc[nt][3] * rcpa(d[nt][3]);                            \
        }                                                                      \
    } while (0)

#define REPACK_CHEAP()                                                         \
    do {                                                                       \
        _Pragma("unroll")                                                      \
        for (int kt = 0; kt < 4; kt++) {                                       \
            ah[kt][0] = packbf(d[2*kt][0],   d[2*kt][1]);                      \
            ah[kt][1] = packbf(d[2*kt][2],   d[2*kt][3]);                      \
            ah[kt][2] = packbf(d[2*kt+1][0], d[2*kt+1][1]);                    \
            ah[kt][3] = packbf(d[2*kt+1][2], d[2*kt+1][3]);                    \
        }                                                                      \
    } while (0)

#define REPACK_FULL()                                                          \
    do {                                                                       \
        _Pragma("unroll")                                                      \
        for (int kt = 0; kt < 4; kt++) {                                       \
            split2(d[2*kt][0],   d[2*kt][1],   ah[kt][0], al[kt][0]);          \
            split2(d[2*kt][2],   d[2*kt][3],   ah[kt][1], al[kt][1]);          \
            split2(d[2*kt+1][0], d[2*kt+1][1], ah[kt][2], al[kt][2]);          \
            split2(d[2*kt+1][2], d[2*kt+1][3], ah[kt][3], al[kt][3]);          \
        }                                                                      \
    } while (0)

    // ---- phase 1: 14 cheap iterations (hi-only, all-register loop body) ----
    #pragma unroll 1
    for (int it = 0; it < CHEAP_ITERS; ++it) {
        MMA_PHASE_CHEAP_R(b0);   // BF-step: d = KT^T(AF) + 1
        BF_NONLIN();             // BF' = rcp(d)
        REPACK_CHEAP();
        MMA_PHASE_CHEAP_R(b2);   // AF-step: d = K'(BF') + 1
        AF_NONLIN();             // AF = AT * rcp(d)
        REPACK_CHEAP();
    }

    // precision boundary: lo residuals start at zero
    #pragma unroll
    for (int kt = 0; kt < 4; kt++)
        #pragma unroll
        for (int r = 0; r < 4; r++) al[kt][r] = 0u;

    // ---- phase 2: 3 precise BF/AF pairs, then final BF ----------------------
    #pragma unroll 1
    for (int it = 0; it < 3; ++it) {
        MMA_PHASE_FULL_R(b0, 1, MMA_ONE);   // BF
        BF_NONLIN();
        REPACK_FULL();
        MMA_PHASE_FULL_R(b2, 3, MMA_ONE);   // AF
        AF_NONLIN();
        REPACK_FULL();
    }

    // final BF step: keep fp32 BF' for the output contraction
    MMA_PHASE_FULL_R(b0, 1, MMA_ONE);
    BF_NONLIN();

    // stash final BF' (fp32) into the AT region (AT dead; same-lane rw)
    #pragma unroll
    for (int nt = 0; nt < 8; nt++) {
        int cb = 8 * nt + 2 * t;
        *reinterpret_cast<float2*>(ats + rlo + cb) =
            make_float2(d[nt][0], d[nt][1]);
        *reinterpret_cast<float2*>(ats + rhi + cb) =
            make_float2(d[nt][2], d[nt][3]);
    }

    // epilogue: H = AF @ M' (C = 0); y = sum_j BF'_j H_j
    MMA_PHASE_FULL_MEM(4, MMA_Z);

    float y0 = 0.f, y1 = 0.f;
    #pragma unroll
    for (int nt = 0; nt < 8; nt++) {
        int cb = 8 * nt + 2 * t;
        float2 blo = *reinterpret_cast<const float2*>(ats + rlo + cb);
        float2 bhi = *reinterpret_cast<const float2*>(ats + rhi + cb);
        y0 = fmaf(blo.x, d[nt][0], fmaf(blo.y, d[nt][1], y0));
        y1 = fmaf(bhi.x, d[nt][2], fmaf(bhi.y, d[nt][3], y1));
    }

    y0 += __shfl_xor_sync(0xFFFFFFFFu, y0, 1);
    y0 += __shfl_xor_sync(0xFFFFFFFFu, y0, 2);
    y1 += __shfl_xor_sync(0xFFFFFFFFu, y1, 1);
    y1 += __shfl_xor_sync(0xFFFFFFFFu, y1, 2);

    if (t == 0) {
        float bc = fminf(fmaxf(braw[0], -10.0f), 10.0f);
        size_t base = (size_t)bid * ROWS_PER_CTA + rb + g;
        out[base + 0] = y0 + bc;
        out[base + 8] = y1 + bc;
    }
}

extern "C" void kernel_launch(void* const* d_in, const int* in_sizes, int n_in,
                              void* d_out, int out_size)
{
    const float* AT    = (const float*)d_in[0];
    const float* Kraw  = (const float*)d_in[1];
    const float* BTraw = (const float*)d_in[2];
    const float* Wraw  = (const float*)d_in[3];
    const float* braw  = (const float*)d_in[4];
    float* out = (float*)d_out;

    const int B = in_sizes[0] / N_DIM;          // 16384
    const int grid = B / ROWS_PER_CTA;          // 128

    cudaFuncSetAttribute(cnet_mma_kernel,
                         cudaFuncAttributeMaxDynamicSharedMemorySize,
                         SMEM_TOTAL);

    cnet_mma_kernel<<<grid, THREADS, SMEM_TOTAL>>>(
        AT, Kraw, BTraw, Wraw, braw, out);
}